// round 3
// baseline (speedup 1.0000x reference)
#include <cuda_runtime.h>
#include <math.h>

// ---------------------------------------------------------------------------
// JointCCSA: sa_loss / s_loss from pairwise Euclidean distances.
//   dists[i][j] = sqrt(max(sq[i] + sq[j] - 2 * X[i].X[j], 0))
//   sa_sum = sum over unordered pairs {i,j}: (y_i==y_j && ds_i!=ds_j) * dist
//   s_sum  = sum over unordered pairs {i,j}: ((y_i<y_j)==(ds_i<ds_j), y/ds differ)
//            * max(0, 1-dist)
//   sa_loss = 0.5*sa_sum/n_sa ; s_loss = 0.5*s_sum/n_s
// Upper-triangular tile sweep only (symmetry) -> half the MACs.
// ---------------------------------------------------------------------------

#define MAX_BS 8192
__device__ float  g_sq[MAX_BS];
__device__ double g_sa_sum;
__device__ double g_s_sum;

// ---------------------------------------------------------------------------
// Kernel 1: per-row squared norms + accumulator init
// ---------------------------------------------------------------------------
__global__ void sq_init_kernel(const float* __restrict__ X, int bs, int d) {
    int row = blockIdx.x;
    if (row == 0 && threadIdx.x == 0) { g_sa_sum = 0.0; g_s_sum = 0.0; }
    if (row >= bs) return;
    const float* xr = X + (size_t)row * d;
    float s = 0.f;
    for (int k = threadIdx.x; k < d; k += blockDim.x) {
        float v = xr[k];
        s = fmaf(v, v, s);
    }
    #pragma unroll
    for (int o = 16; o > 0; o >>= 1) s += __shfl_down_sync(0xffffffff, s, o);
    __shared__ float ws[8];
    int lane = threadIdx.x & 31, w = threadIdx.x >> 5;
    if (lane == 0) ws[w] = s;
    __syncthreads();
    if (threadIdx.x == 0) {
        float t = 0.f;
        int nw = (blockDim.x + 31) >> 5;
        for (int i = 0; i < nw; i++) t += ws[i];
        g_sq[row] = t;
    }
}

// ---------------------------------------------------------------------------
// Kernel 2: tiled Gram + distance + masked reduction (upper-tri tiles)
// ---------------------------------------------------------------------------
#define TILE 128
#define KS   16

__global__ __launch_bounds__(256) void pair_kernel(
    const float* __restrict__ X,
    const int*   __restrict__ ds,
    const int*   __restrict__ y,
    int bs, int d, int nt)
{
    __shared__ float As[KS][TILE];
    __shared__ float Bs[KS][TILE];

    // Decode upper-triangular (bi, bj) from linear block id.
    int t = blockIdx.x, bi = 0, rem = nt;
    while (t >= rem) { t -= rem; bi++; rem--; }
    int bj = bi + t;

    const int tid = threadIdx.x;
    const int tx = tid & 15;
    const int ty = tid >> 4;

    float acc[8][8];
    #pragma unroll
    for (int u = 0; u < 8; u++)
        #pragma unroll
        for (int v = 0; v < 8; v++) acc[u][v] = 0.f;

    const int row_i_base = bi * TILE;
    const int row_j_base = bj * TILE;

    for (int k0 = 0; k0 < d; k0 += KS) {
        // cooperative load: 128 rows x 16 k per side, 512 float4 / side
        #pragma unroll
        for (int it = 0; it < 2; it++) {
            int lin = tid + 256 * it;        // 0..511
            int r   = lin & 127;             // row within tile
            int kc  = lin >> 7;              // float4 index 0..3
            int kk  = k0 + kc * 4;

            float4 v = make_float4(0.f, 0.f, 0.f, 0.f);
            int gi = row_i_base + r;
            if (gi < bs) {
                if (kk + 3 < d) {
                    v = *(const float4*)(X + (size_t)gi * d + kk);
                } else {
                    const float* p = X + (size_t)gi * d;
                    if (kk + 0 < d) v.x = p[kk + 0];
                    if (kk + 1 < d) v.y = p[kk + 1];
                    if (kk + 2 < d) v.z = p[kk + 2];
                    if (kk + 3 < d) v.w = p[kk + 3];
                }
            }
            As[kc * 4 + 0][r] = v.x; As[kc * 4 + 1][r] = v.y;
            As[kc * 4 + 2][r] = v.z; As[kc * 4 + 3][r] = v.w;

            float4 w = make_float4(0.f, 0.f, 0.f, 0.f);
            int gj = row_j_base + r;
            if (gj < bs) {
                if (kk + 3 < d) {
                    w = *(const float4*)(X + (size_t)gj * d + kk);
                } else {
                    const float* p = X + (size_t)gj * d;
                    if (kk + 0 < d) w.x = p[kk + 0];
                    if (kk + 1 < d) w.y = p[kk + 1];
                    if (kk + 2 < d) w.z = p[kk + 2];
                    if (kk + 3 < d) w.w = p[kk + 3];
                }
            }
            Bs[kc * 4 + 0][r] = w.x; Bs[kc * 4 + 1][r] = w.y;
            Bs[kc * 4 + 2][r] = w.z; Bs[kc * 4 + 3][r] = w.w;
        }
        __syncthreads();

        #pragma unroll
        for (int k = 0; k < KS; k++) {
            float a[8], b[8];
            *(float4*)&a[0] = *(const float4*)&As[k][ty * 4];
            *(float4*)&a[4] = *(const float4*)&As[k][64 + ty * 4];
            *(float4*)&b[0] = *(const float4*)&Bs[k][tx * 4];
            *(float4*)&b[4] = *(const float4*)&Bs[k][64 + tx * 4];
            #pragma unroll
            for (int u = 0; u < 8; u++)
                #pragma unroll
                for (int v = 0; v < 8; v++)
                    acc[u][v] = fmaf(a[u], b[v], acc[u][v]);
        }
        __syncthreads();
    }

    // ---- epilogue: distances + masks ----
    int ri[8], cj[8];
    #pragma unroll
    for (int u = 0; u < 8; u++) {
        ri[u] = row_i_base + ((u < 4) ? (ty * 4 + u) : (64 + ty * 4 + (u - 4)));
        cj[u] = row_j_base + ((u < 4) ? (tx * 4 + u) : (64 + tx * 4 + (u - 4)));
    }

    float sqi[8], sqj[8];
    int yi[8], yj[8], di[8], dj[8];
    #pragma unroll
    for (int u = 0; u < 8; u++) {
        int i = ri[u];
        bool ok = (i < bs);
        sqi[u] = ok ? g_sq[i] : 0.f;
        yi[u]  = ok ? y[i]    : -1;
        di[u]  = ok ? ds[i]   : -1;
        int j = cj[u];
        bool okj = (j < bs);
        sqj[u] = okj ? g_sq[j] : 0.f;
        yj[u]  = okj ? y[j]    : -2;
        dj[u]  = okj ? ds[j]   : -2;
    }

    float sa_acc = 0.f, s_acc = 0.f;
    const bool diag = (bi == bj);
    #pragma unroll
    for (int u = 0; u < 8; u++) {
        #pragma unroll
        for (int v = 0; v < 8; v++) {
            int i = ri[u], j = cj[v];
            if (i >= bs || j >= bs) continue;
            if (diag && j <= i) continue;
            float d2 = sqi[u] + sqj[v] - 2.f * acc[u][v];
            float dist = sqrtf(fmaxf(d2, 0.f));
            bool ddiff = (di[u] != dj[v]);
            if (ddiff && yi[u] == yj[v]) sa_acc += dist;
            if (ddiff && yi[u] != yj[v] &&
                ((yi[u] < yj[v]) == (di[u] < dj[v])))
                s_acc += fmaxf(0.f, 1.f - dist);
        }
    }

    // ---- block reduction ----
    #pragma unroll
    for (int o = 16; o > 0; o >>= 1) {
        sa_acc += __shfl_down_sync(0xffffffff, sa_acc, o);
        s_acc  += __shfl_down_sync(0xffffffff, s_acc,  o);
    }
    __shared__ float rsa[8], rs[8];
    int lane = tid & 31, w = tid >> 5;
    if (lane == 0) { rsa[w] = sa_acc; rs[w] = s_acc; }
    __syncthreads();
    if (tid == 0) {
        float tsa = 0.f, tss = 0.f;
        #pragma unroll
        for (int i = 0; i < 8; i++) { tsa += rsa[i]; tss += rs[i]; }
        atomicAdd(&g_sa_sum, (double)tsa);
        atomicAdd(&g_s_sum,  (double)tss);
    }
}

// ---------------------------------------------------------------------------
// Kernel 3: finalize
// ---------------------------------------------------------------------------
__global__ void finalize_kernel(const int* pnc, const int* pnd, float* out) {
    int nc = pnc ? *pnc : 4;
    int nd = pnd ? *pnd : 3;
    int dpairs = nd * (nd - 1) / 2;
    double n_sa = (double)nc * dpairs;
    double n_s  = (double)(nc * (nc - 1) / 2) * dpairs;
    out[0] = (float)(0.5 * g_sa_sum / n_sa);
    out[1] = (float)(0.5 * g_s_sum  / n_s);
}

// ---------------------------------------------------------------------------
extern "C" void kernel_launch(void* const* d_in, const int* in_sizes, int n_in,
                              void* d_out, int out_size) {
    const float* X  = (const float*)d_in[0];
    const int*   ds = (const int*)d_in[1];
    const int*   y  = (const int*)d_in[2];
    const int* pnc = (n_in >= 5) ? (const int*)d_in[3] : nullptr;
    const int* pnd = (n_in >= 5) ? (const int*)d_in[4] : nullptr;

    int bs = in_sizes[1];
    int d  = in_sizes[0] / bs;
    int nt = (bs + TILE - 1) / TILE;
    int nblocks = nt * (nt + 1) / 2;

    sq_init_kernel<<<bs, 128>>>(X, bs, d);
    pair_kernel<<<nblocks, 256>>>(X, ds, y, bs, d, nt);
    finalize_kernel<<<1, 1>>>(pnc, pnd, (float*)d_out);
}

// round 6
// speedup vs baseline: 5.6809x; 5.6809x over previous
#include <cuda_runtime.h>
#include <cuda_fp16.h>
#include <math.h>
#include <cstdint>
#include <limits.h>

// ---------------------------------------------------------------------------
// JointCCSA via fp16 mma.sync (HMMA) Gram matrix, fp32 accumulate.
//   dist[i][j] = sqrt(max(sq_i + sq_j - 2 * X_i.X_j, 0))
//   sa_sum += dist           where y_i==y_j && ds_i!=ds_j   (unordered pairs)
//   s_sum  += max(0,1-dist)  where y_i!=y_j && ds_i!=ds_j && (y_i<y_j)==(ds_i<ds_j)
// Upper-triangular 128x128 tile sweep (528 CTAs for bs=4096).
// NOTE: tcgen05 is unavailable (harness PTX targets plain sm_103, no 'a'
// features), so the tensor path is mma.sync + ldmatrix + cp.async.
// ---------------------------------------------------------------------------

#define MAX_BS 4096
#define MAX_D  512
#define TILE   128
#define KCHUNK 64
#define ROWH   72          // halfs per smem row (64 data + 8 pad)
#define ROWB   (ROWH * 2)  // 144 bytes: 8 rows hit 8 distinct 16B groups

__device__ float  g_sq[MAX_BS];
__device__ __half g_h[MAX_BS * MAX_D];
__device__ double g_sa_sum;
__device__ double g_s_sum;

__device__ __forceinline__ uint32_t smem_u32(const void* p) {
    uint32_t a;
    asm("{ .reg .u64 t; cvta.to.shared.u64 t, %1; cvt.u32.u64 %0, t; }" : "=r"(a) : "l"(p));
    return a;
}
__device__ __forceinline__ void cp16(uint32_t saddr, const void* g) {
    asm volatile("cp.async.cg.shared.global [%0], [%1], 16;" :: "r"(saddr), "l"(g));
}
__device__ __forceinline__ void ldmatrix_x4(uint32_t* r, uint32_t addr) {
    asm volatile("ldmatrix.sync.aligned.m8n8.x4.shared.b16 {%0,%1,%2,%3}, [%4];"
                 : "=r"(r[0]), "=r"(r[1]), "=r"(r[2]), "=r"(r[3]) : "r"(addr));
}
__device__ __forceinline__ void mma16816(float* c, const uint32_t* a,
                                         uint32_t b0, uint32_t b1) {
    asm volatile(
        "mma.sync.aligned.m16n8k16.row.col.f32.f16.f16.f32 "
        "{%0,%1,%2,%3}, {%4,%5,%6,%7}, {%8,%9}, {%0,%1,%2,%3};"
        : "+f"(c[0]), "+f"(c[1]), "+f"(c[2]), "+f"(c[3])
        : "r"(a[0]), "r"(a[1]), "r"(a[2]), "r"(a[3]), "r"(b0), "r"(b1));
}

// ---------------------------------------------------------------------------
// Kernel 1: fp16 convert + exact fp32 row norms + accumulator init
// ---------------------------------------------------------------------------
__global__ void prep_kernel(const float* __restrict__ X, int bs, int d) {
    int row = blockIdx.x;
    if (row == 0 && threadIdx.x == 0) { g_sa_sum = 0.0; g_s_sum = 0.0; }

    float s = 0.f;
    for (int k = threadIdx.x; k < MAX_D; k += blockDim.x) {
        float x = 0.f;
        if (row < bs && k < d) x = X[(size_t)row * d + k];
        g_h[(size_t)row * MAX_D + k] = __float2half_rn(x);
        s = fmaf(x, x, s);
    }
    #pragma unroll
    for (int o = 16; o > 0; o >>= 1) s += __shfl_down_sync(0xffffffff, s, o);
    __shared__ float ws[4];
    int lane = threadIdx.x & 31, w = threadIdx.x >> 5;
    if (lane == 0) ws[w] = s;
    __syncthreads();
    if (threadIdx.x == 0) g_sq[row] = ws[0] + ws[1] + ws[2] + ws[3];
}

// ---------------------------------------------------------------------------
// Kernel 2: mma.sync tiled Gram + distance + masked reduction
// ---------------------------------------------------------------------------
// dyn smem (bytes):
//   A0 18432 | A1 18432 | B0 18432 | B1 18432          (128 rows x 144B)
//   isq 512 | jsq 512 | iy 512 | jy 512 | id 512 | jd 512
//   red 64
#define OFF_A0 0
#define OFF_A1 18432
#define OFF_B0 36864
#define OFF_B1 55296
#define OFF_META 73728
#define SMEM_TOTAL (OFF_META + 6 * 512 + 64)

__global__ __launch_bounds__(256) void pair_mma_kernel(
    const int* __restrict__ ds,
    const int* __restrict__ y,
    int bs, int d, int nt)
{
    extern __shared__ char smem[];
    const uint32_t sbase = smem_u32(smem);
    float* isq_s = (float*)(smem + OFF_META);
    float* jsq_s = isq_s + TILE;
    int*   iy_s  = (int*)(jsq_s + TILE);
    int*   jy_s  = iy_s + TILE;
    int*   id_s  = jy_s + TILE;
    int*   jd_s  = id_s + TILE;
    float* red_s = (float*)(jd_s + TILE);

    const int tid = threadIdx.x;
    const int wid = tid >> 5, lane = tid & 31;

    // decode upper-tri (bi, bj)
    int t = blockIdx.x, bi = 0, rem = nt;
    while (t >= rem) { t -= rem; bi++; rem--; }
    const int bj = bi + t;
    const int row_i_base = bi * TILE;
    const int row_j_base = bj * TILE;
    const bool diag = (bi == bj);

    // metadata
    if (tid < TILE) {
        int i = row_i_base + tid;
        int j = row_j_base + tid;
        bool oi = (i < bs), oj = (j < bs);
        isq_s[tid] = oi ? g_sq[i] : 0.f;
        iy_s[tid]  = oi ? y[i]  : INT_MIN;
        id_s[tid]  = oi ? ds[i] : INT_MIN;
        jsq_s[tid] = oj ? g_sq[j] : 0.f;
        jy_s[tid]  = oj ? y[j]  : INT_MIN;
        jd_s[tid]  = oj ? ds[j] : INT_MIN;
    }

    const int nchunks = (d + KCHUNK - 1) / KCHUNK;   // 8 for d=512

    // chunk copy: 256 threads x 4 iters -> 1024 x 16B per (A|B) tile pair half
    auto issue_chunk = [&](int c) {
        const uint32_t aoff = (c & 1) ? OFF_A1 : OFF_A0;
        const uint32_t boff = (c & 1) ? OFF_B1 : OFF_B0;
        const int k0 = c * KCHUNK;
        #pragma unroll
        for (int it = 0; it < 4; it++) {
            int lin = tid + 256 * it;      // 0..1023
            int r   = lin >> 3;
            int cb  = lin & 7;
            uint32_t so = (uint32_t)(r * ROWB + cb * 16);
            cp16(sbase + aoff + so,
                 g_h + (size_t)(row_i_base + r) * MAX_D + k0 + cb * 8);
            cp16(sbase + boff + so,
                 g_h + (size_t)(row_j_base + r) * MAX_D + k0 + cb * 8);
        }
        asm volatile("cp.async.commit_group;" ::: "memory");
    };

    issue_chunk(0);

    // warp tiling: warp_m in {0,1} (64 rows), warp_n in {0..3} (32 cols)
    const int warp_m = wid & 1;
    const int warp_n = wid >> 1;

    // ldmatrix lane address components
    const int la_r = (lane & 7) + ((lane >> 3) & 1) * 8;  // A: row-in-16 block
    const int la_k = ((lane >> 4) & 1) * 8;               // A: k offset
    const int lb_n = (lane & 7) + ((lane >> 4) & 1) * 8;  // B: col-in-16 block
    const int lb_k = ((lane >> 3) & 1) * 8;               // B: k offset

    float c[4][4][4];
    #pragma unroll
    for (int mt = 0; mt < 4; mt++)
        #pragma unroll
        for (int ntl = 0; ntl < 4; ntl++)
            #pragma unroll
            for (int r = 0; r < 4; r++) c[mt][ntl][r] = 0.f;

    for (int ck = 0; ck < nchunks; ck++) {
        if (ck + 1 < nchunks) {
            issue_chunk(ck + 1);
            asm volatile("cp.async.wait_group 1;" ::: "memory");
        } else {
            asm volatile("cp.async.wait_group 0;" ::: "memory");
        }
        __syncthreads();

        const uint32_t aoff = (ck & 1) ? OFF_A1 : OFF_A0;
        const uint32_t boff = (ck & 1) ? OFF_B1 : OFF_B0;
        const uint32_t abase = sbase + aoff + (uint32_t)((warp_m * 64 + la_r) * ROWB + la_k * 2);
        const uint32_t bbase = sbase + boff + (uint32_t)((warp_n * 32 + lb_n) * ROWB + lb_k * 2);

        #pragma unroll
        for (int ks = 0; ks < KCHUNK; ks += 16) {
            uint32_t a[4][4];
            #pragma unroll
            for (int mt = 0; mt < 4; mt++)
                ldmatrix_x4(a[mt], abase + (uint32_t)(mt * 16 * ROWB + ks * 2));
            uint32_t b[2][4];
            #pragma unroll
            for (int np = 0; np < 2; np++)
                ldmatrix_x4(b[np], bbase + (uint32_t)(np * 16 * ROWB + ks * 2));
            #pragma unroll
            for (int mt = 0; mt < 4; mt++)
                #pragma unroll
                for (int ntl = 0; ntl < 4; ntl++)
                    mma16816(c[mt][ntl], a[mt],
                             b[ntl >> 1][(ntl & 1) * 2],
                             b[ntl >> 1][(ntl & 1) * 2 + 1]);
        }
        __syncthreads();
    }

    // ---- epilogue: distances + masks from register fragments ----
    const int tr = lane >> 2;       // 0..7
    const int tc = lane & 3;        // 0..3
    float sa_acc = 0.f, s_acc = 0.f;

    #pragma unroll
    for (int mt = 0; mt < 4; mt++) {
        #pragma unroll
        for (int rh = 0; rh < 2; rh++) {       // row half of C frag
            const int i_local = warp_m * 64 + mt * 16 + tr + rh * 8;
            const int i = row_i_base + i_local;
            if (i >= bs) continue;
            const float sqi = isq_s[i_local];
            const int yi = iy_s[i_local], di = id_s[i_local];
            #pragma unroll
            for (int ntl = 0; ntl < 4; ntl++) {
                #pragma unroll
                for (int cpair = 0; cpair < 2; cpair++) {
                    const int j_local = warp_n * 32 + ntl * 8 + tc * 2 + cpair;
                    const int j = row_j_base + j_local;
                    if (j >= bs) continue;
                    if (diag && j_local <= i_local) continue;
                    const float dot = c[mt][ntl][rh * 2 + cpair];
                    const float d2 = sqi + jsq_s[j_local] - 2.f * dot;
                    const float dist = sqrtf(fmaxf(d2, 0.f));
                    const int yj = jy_s[j_local], dj = jd_s[j_local];
                    const bool ddiff = (di != dj);
                    if (ddiff && yi == yj) sa_acc += dist;
                    if (ddiff && yi != yj && ((yi < yj) == (di < dj)))
                        s_acc += fmaxf(0.f, 1.f - dist);
                }
            }
        }
    }

    // block reduction + global accumulate
    #pragma unroll
    for (int o = 16; o > 0; o >>= 1) {
        sa_acc += __shfl_down_sync(0xffffffff, sa_acc, o);
        s_acc  += __shfl_down_sync(0xffffffff, s_acc,  o);
    }
    if (lane == 0) { red_s[wid] = sa_acc; red_s[8 + wid] = s_acc; }
    __syncthreads();
    if (tid == 0) {
        float tsa = 0.f, tss = 0.f;
        #pragma unroll
        for (int k = 0; k < 8; k++) { tsa += red_s[k]; tss += red_s[8 + k]; }
        atomicAdd(&g_sa_sum, (double)tsa);
        atomicAdd(&g_s_sum,  (double)tss);
    }
}

// ---------------------------------------------------------------------------
// Kernel 3: finalize
// ---------------------------------------------------------------------------
__global__ void finalize_kernel(const int* pnc, const int* pnd, float* out) {
    int nc = pnc ? *pnc : 4;
    int nd = pnd ? *pnd : 3;
    int dpairs = nd * (nd - 1) / 2;
    double n_sa = (double)nc * dpairs;
    double n_s  = (double)(nc * (nc - 1) / 2) * dpairs;
    out[0] = (float)(0.5 * g_sa_sum / n_sa);
    out[1] = (float)(0.5 * g_s_sum  / n_s);
}

// ---------------------------------------------------------------------------
extern "C" void kernel_launch(void* const* d_in, const int* in_sizes, int n_in,
                              void* d_out, int out_size) {
    const float* X  = (const float*)d_in[0];
    const int*   ds = (const int*)d_in[1];
    const int*   y  = (const int*)d_in[2];
    const int* pnc = (n_in >= 5) ? (const int*)d_in[3] : nullptr;
    const int* pnd = (n_in >= 5) ? (const int*)d_in[4] : nullptr;

    int bs = in_sizes[1];
    int d  = in_sizes[0] / bs;
    if (bs > MAX_BS) bs = MAX_BS;   // dataset shape is 4096x512
    if (d  > MAX_D)  d  = MAX_D;
    int nt = (bs + TILE - 1) / TILE;
    int nblocks = nt * (nt + 1) / 2;

    cudaFuncSetAttribute(pair_mma_kernel,
                         cudaFuncAttributeMaxDynamicSharedMemorySize, SMEM_TOTAL);

    prep_kernel<<<MAX_BS, 128>>>(X, bs, d);
    pair_mma_kernel<<<nblocks, 256, SMEM_TOTAL>>>(ds, y, bs, d, nt);
    finalize_kernel<<<1, 1>>>(pnc, pnd, (float*)d_out);
}

// round 8
// speedup vs baseline: 5.8927x; 1.0373x over previous
#include <cuda_runtime.h>
#include <cuda_fp16.h>
#include <math.h>
#include <cstdint>
#include <limits.h>

// ---------------------------------------------------------------------------
// JointCCSA via fp16 mma.sync (HMMA) Gram matrix, fp32 accumulate.
//   dist[i][j] = sqrt(max(sq_i + sq_j - 2 * X_i.X_j, 0))
//   sa_sum += dist           where y_i==y_j && ds_i!=ds_j   (unordered pairs)
//   s_sum  += max(0,1-dist)  where y_i!=y_j && ds_i!=ds_j && (y_i<y_j)==(ds_i<ds_j)
// Upper-triangular 128x128 tile sweep; 2 CTAs/SM; fused finalize.
// ---------------------------------------------------------------------------

#define MAX_BS 4096
#define MAX_D  512
#define TILE   128
#define KCHUNK 64
#define ROWH   72          // halfs per smem row (64 data + 8 pad)
#define ROWB   (ROWH * 2)  // 144 bytes: 8 rows hit 8 distinct 16B groups

__device__ float  g_sq[MAX_BS];
__device__ __half g_h[MAX_BS * MAX_D];
__device__ double g_sa_sum;
__device__ double g_s_sum;
__device__ unsigned int g_done;

__device__ __forceinline__ uint32_t smem_u32(const void* p) {
    uint32_t a;
    asm("{ .reg .u64 t; cvta.to.shared.u64 t, %1; cvt.u32.u64 %0, t; }" : "=r"(a) : "l"(p));
    return a;
}
__device__ __forceinline__ void cp16(uint32_t saddr, const void* g) {
    asm volatile("cp.async.cg.shared.global [%0], [%1], 16;" :: "r"(saddr), "l"(g));
}
__device__ __forceinline__ void ldmatrix_x4(uint32_t* r, uint32_t addr) {
    asm volatile("ldmatrix.sync.aligned.m8n8.x4.shared.b16 {%0,%1,%2,%3}, [%4];"
                 : "=r"(r[0]), "=r"(r[1]), "=r"(r[2]), "=r"(r[3]) : "r"(addr));
}
__device__ __forceinline__ void mma16816(float* c, const uint32_t* a,
                                         uint32_t b0, uint32_t b1) {
    asm volatile(
        "mma.sync.aligned.m16n8k16.row.col.f32.f16.f16.f32 "
        "{%0,%1,%2,%3}, {%4,%5,%6,%7}, {%8,%9}, {%0,%1,%2,%3};"
        : "+f"(c[0]), "+f"(c[1]), "+f"(c[2]), "+f"(c[3])
        : "r"(a[0]), "r"(a[1]), "r"(a[2]), "r"(a[3]), "r"(b0), "r"(b1));
}

// ---------------------------------------------------------------------------
// Kernel 1: fp16 convert + exact fp32 row norms + accumulator init
// one block per row, one float4 per thread (d=512, 128 threads)
// ---------------------------------------------------------------------------
__global__ __launch_bounds__(128) void prep_kernel(const float* __restrict__ X,
                                                   int bs, int d) {
    const int row = blockIdx.x;
    if (row == 0 && threadIdx.x == 0) {
        g_sa_sum = 0.0; g_s_sum = 0.0; g_done = 0u;
    }
    float s = 0.f;
    if (d == MAX_D) {
        const int k = threadIdx.x * 4;
        float4 v = make_float4(0.f, 0.f, 0.f, 0.f);
        if (row < bs) v = *(const float4*)(X + (size_t)row * MAX_D + k);
        __half2 h01 = __floats2half2_rn(v.x, v.y);
        __half2 h23 = __floats2half2_rn(v.z, v.w);
        *(uint2*)(g_h + (size_t)row * MAX_D + k) =
            make_uint2(*(uint32_t*)&h01, *(uint32_t*)&h23);
        s = v.x * v.x + v.y * v.y + v.z * v.z + v.w * v.w;
    } else {
        for (int k = threadIdx.x; k < MAX_D; k += blockDim.x) {
            float x = 0.f;
            if (row < bs && k < d) x = X[(size_t)row * d + k];
            g_h[(size_t)row * MAX_D + k] = __float2half_rn(x);
            s = fmaf(x, x, s);
        }
    }
    #pragma unroll
    for (int o = 16; o > 0; o >>= 1) s += __shfl_down_sync(0xffffffff, s, o);
    __shared__ float ws[4];
    int lane = threadIdx.x & 31, w = threadIdx.x >> 5;
    if (lane == 0) ws[w] = s;
    __syncthreads();
    if (threadIdx.x == 0) g_sq[row] = ws[0] + ws[1] + ws[2] + ws[3];
}

// ---------------------------------------------------------------------------
// Kernel 2: mma.sync tiled Gram + distance + masked reduction + finalize
// ---------------------------------------------------------------------------
#define OFF_A0 0
#define OFF_A1 18432
#define OFF_B0 36864
#define OFF_B1 55296
#define OFF_META 73728
#define SMEM_TOTAL (OFF_META + 6 * 512 + 64)

__global__ __launch_bounds__(256, 2) void pair_mma_kernel(
    const int* __restrict__ ds,
    const int* __restrict__ y,
    const int* __restrict__ pnc,
    const int* __restrict__ pnd,
    float* __restrict__ out,
    int bs, int d, int nt, int nblocks)
{
    extern __shared__ char smem[];
    const uint32_t sbase = smem_u32(smem);
    float* isq_s = (float*)(smem + OFF_META);
    float* jsq_s = isq_s + TILE;
    int*   iy_s  = (int*)(jsq_s + TILE);
    int*   jy_s  = iy_s + TILE;
    int*   id_s  = jy_s + TILE;
    int*   jd_s  = id_s + TILE;
    float* red_s = (float*)(jd_s + TILE);

    const int tid = threadIdx.x;
    const int wid = tid >> 5, lane = tid & 31;

    // decode upper-tri (bi, bj)
    int t = blockIdx.x, bi = 0, rem = nt;
    while (t >= rem) { t -= rem; bi++; rem--; }
    const int bj = bi + t;
    const int row_i_base = bi * TILE;
    const int row_j_base = bj * TILE;
    const bool diag = (bi == bj);

    // metadata
    if (tid < TILE) {
        int i = row_i_base + tid;
        int j = row_j_base + tid;
        bool oi = (i < bs), oj = (j < bs);
        isq_s[tid] = oi ? g_sq[i] : 0.f;
        iy_s[tid]  = oi ? y[i]  : INT_MIN;
        id_s[tid]  = oi ? ds[i] : INT_MIN;
        jsq_s[tid] = oj ? g_sq[j] : 0.f;
        jy_s[tid]  = oj ? y[j]  : INT_MIN;
        jd_s[tid]  = oj ? ds[j] : INT_MIN;
    }

    const int nchunks = (d + KCHUNK - 1) / KCHUNK;   // 8 for d=512

    auto issue_chunk = [&](int c) {
        const uint32_t aoff = (c & 1) ? OFF_A1 : OFF_A0;
        const uint32_t boff = (c & 1) ? OFF_B1 : OFF_B0;
        const int k0 = c * KCHUNK;
        #pragma unroll
        for (int it = 0; it < 4; it++) {
            int lin = tid + 256 * it;      // 0..1023
            int r   = lin >> 3;
            int cb  = lin & 7;
            uint32_t so = (uint32_t)(r * ROWB + cb * 16);
            cp16(sbase + aoff + so,
                 g_h + (size_t)(row_i_base + r) * MAX_D + k0 + cb * 8);
            cp16(sbase + boff + so,
                 g_h + (size_t)(row_j_base + r) * MAX_D + k0 + cb * 8);
        }
        asm volatile("cp.async.commit_group;" ::: "memory");
    };

    issue_chunk(0);

    const int warp_m = wid & 1;
    const int warp_n = wid >> 1;
    const int la_r = (lane & 7) + ((lane >> 3) & 1) * 8;
    const int la_k = ((lane >> 4) & 1) * 8;
    const int lb_n = (lane & 7) + ((lane >> 4) & 1) * 8;
    const int lb_k = ((lane >> 3) & 1) * 8;

    float c[4][4][4];
    #pragma unroll
    for (int mt = 0; mt < 4; mt++)
        #pragma unroll
        for (int ntl = 0; ntl < 4; ntl++)
            #pragma unroll
            for (int r = 0; r < 4; r++) c[mt][ntl][r] = 0.f;

    for (int ck = 0; ck < nchunks; ck++) {
        if (ck + 1 < nchunks) {
            issue_chunk(ck + 1);
            asm volatile("cp.async.wait_group 1;" ::: "memory");
        } else {
            asm volatile("cp.async.wait_group 0;" ::: "memory");
        }
        __syncthreads();

        const uint32_t aoff = (ck & 1) ? OFF_A1 : OFF_A0;
        const uint32_t boff = (ck & 1) ? OFF_B1 : OFF_B0;
        const uint32_t abase = sbase + aoff + (uint32_t)((warp_m * 64 + la_r) * ROWB + la_k * 2);
        const uint32_t bbase = sbase + boff + (uint32_t)((warp_n * 32 + lb_n) * ROWB + lb_k * 2);

        #pragma unroll
        for (int ks = 0; ks < KCHUNK; ks += 16) {
            uint32_t a[4][4];
            #pragma unroll
            for (int mt = 0; mt < 4; mt++)
                ldmatrix_x4(a[mt], abase + (uint32_t)(mt * 16 * ROWB + ks * 2));
            uint32_t b[2][4];
            #pragma unroll
            for (int np = 0; np < 2; np++)
                ldmatrix_x4(b[np], bbase + (uint32_t)(np * 16 * ROWB + ks * 2));
            #pragma unroll
            for (int mt = 0; mt < 4; mt++)
                #pragma unroll
                for (int ntl = 0; ntl < 4; ntl++)
                    mma16816(c[mt][ntl], a[mt],
                             b[ntl >> 1][(ntl & 1) * 2],
                             b[ntl >> 1][(ntl & 1) * 2 + 1]);
        }
        __syncthreads();
    }

    // ---- epilogue: distances + masks from register fragments ----
    const int tr = lane >> 2;
    const int tc = lane & 3;
    float sa_acc = 0.f, s_acc = 0.f;

    #pragma unroll
    for (int mt = 0; mt < 4; mt++) {
        #pragma unroll
        for (int rh = 0; rh < 2; rh++) {
            const int i_local = warp_m * 64 + mt * 16 + tr + rh * 8;
            const int i = row_i_base + i_local;
            if (i >= bs) continue;
            const float sqi = isq_s[i_local];
            const int yi = iy_s[i_local], di = id_s[i_local];
            #pragma unroll
            for (int ntl = 0; ntl < 4; ntl++) {
                #pragma unroll
                for (int cpair = 0; cpair < 2; cpair++) {
                    const int j_local = warp_n * 32 + ntl * 8 + tc * 2 + cpair;
                    const int j = row_j_base + j_local;
                    if (j >= bs) continue;
                    if (diag && j_local <= i_local) continue;
                    const float dot = c[mt][ntl][rh * 2 + cpair];
                    const float d2 = sqi + jsq_s[j_local] - 2.f * dot;
                    const float dist = sqrtf(fmaxf(d2, 0.f));
                    const int yj = jy_s[j_local], dj = jd_s[j_local];
                    const bool ddiff = (di != dj);
                    if (ddiff && yi == yj) sa_acc += dist;
                    if (ddiff && yi != yj && ((yi < yj) == (di < dj)))
                        s_acc += fmaxf(0.f, 1.f - dist);
                }
            }
        }
    }

    // block reduction + global accumulate
    #pragma unroll
    for (int o = 16; o > 0; o >>= 1) {
        sa_acc += __shfl_down_sync(0xffffffff, sa_acc, o);
        s_acc  += __shfl_down_sync(0xffffffff, s_acc,  o);
    }
    if (lane == 0) { red_s[wid] = sa_acc; red_s[8 + wid] = s_acc; }
    __syncthreads();
    if (tid == 0) {
        float tsa = 0.f, tss = 0.f;
        #pragma unroll
        for (int k = 0; k < 8; k++) { tsa += red_s[k]; tss += red_s[8 + k]; }
        atomicAdd(&g_sa_sum, (double)tsa);
        atomicAdd(&g_s_sum,  (double)tss);
        __threadfence();
        unsigned int prev = atomicAdd(&g_done, 1u);
        if (prev == (unsigned int)(nblocks - 1)) {
            // last CTA finalizes
            int nc = pnc ? *pnc : 4;
            int nd = pnd ? *pnd : 3;
            int dpairs = nd * (nd - 1) / 2;
            double n_sa = (double)nc * dpairs;
            double n_s  = (double)(nc * (nc - 1) / 2) * dpairs;
            out[0] = (float)(0.5 * g_sa_sum / n_sa);
            out[1] = (float)(0.5 * g_s_sum  / n_s);
        }
    }
}

// ---------------------------------------------------------------------------
extern "C" void kernel_launch(void* const* d_in, const int* in_sizes, int n_in,
                              void* d_out, int out_size) {
    const float* X  = (const float*)d_in[0];
    const int*   ds = (const int*)d_in[1];
    const int*   y  = (const int*)d_in[2];
    const int* pnc = (n_in >= 5) ? (const int*)d_in[3] : nullptr;
    const int* pnd = (n_in >= 5) ? (const int*)d_in[4] : nullptr;

    int bs = in_sizes[1];
    int d  = in_sizes[0] / bs;
    if (bs > MAX_BS) bs = MAX_BS;   // dataset shape is 4096x512
    if (d  > MAX_D)  d  = MAX_D;
    int nt = (bs + TILE - 1) / TILE;
    int nblocks = nt * (nt + 1) / 2;

    cudaFuncSetAttribute(pair_mma_kernel,
                         cudaFuncAttributeMaxDynamicSharedMemorySize, SMEM_TOTAL);

    prep_kernel<<<MAX_BS, 128>>>(X, bs, d);
    pair_mma_kernel<<<nblocks, 256, SMEM_TOTAL>>>(ds, y, pnc, pnd, (float*)d_out,
                                                  bs, d, nt, nblocks);
}